// round 1
// baseline (speedup 1.0000x reference)
#include <cuda_runtime.h>

#define NHX 64
#define NHY 64
#define NU  512
#define NV  512
#define LCH 16   // latent per plane
#define NPLANES 6

// Compute wrap-around bilinear axis: i1, i2, frac — matches reference semantics
// (where(ind==I, I-1, ind); i1=floor; i2=(i1+1)%I).
__device__ __forceinline__ void axis(float ind, int I, int& i1, int& i2, float& fr) {
    if (ind == (float)I) ind = (float)(I - 1);
    i1 = (int)ind;              // ind >= 0, truncation == floor
    fr = ind - (float)i1;
    i2 = i1 + 1;
    if (i2 == I) i2 = 0;
}

// One float4 (4 of 16 channels, selected by q) of a bilinear interp on plane F[M,I,J,L].
__device__ __forceinline__ float4 bilerp4(const float* __restrict__ F,
                                          int mi, int I, int J,
                                          int i1, int i2, float ir,
                                          int j1, int j2, float jr, int q) {
    int rowA = (mi * I + i1) * J;
    int rowB = (mi * I + i2) * J;
    const float4* p11 = reinterpret_cast<const float4*>(F + (size_t)(rowA + j1) * LCH) + q;
    const float4* p21 = reinterpret_cast<const float4*>(F + (size_t)(rowB + j1) * LCH) + q;
    const float4* p12 = reinterpret_cast<const float4*>(F + (size_t)(rowA + j2) * LCH) + q;
    const float4* p22 = reinterpret_cast<const float4*>(F + (size_t)(rowB + j2) * LCH) + q;
    float4 a = __ldg(p11);
    float4 b = __ldg(p21);
    float4 c = __ldg(p12);
    float4 d = __ldg(p22);
    float omi = 1.0f - ir;
    float omj = 1.0f - jr;
    float4 out;
    // match reference: top = a*(1-ir)+b*ir; bot = c*(1-ir)+d*ir; res = top*(1-jr)+bot*jr
    out.x = (a.x * omi + b.x * ir) * omj + (c.x * omi + d.x * ir) * jr;
    out.y = (a.y * omi + b.y * ir) * omj + (c.y * omi + d.y * ir) * jr;
    out.z = (a.z * omi + b.z * ir) * omj + (c.z * omi + d.z * ir) * jr;
    out.w = (a.w * omi + b.w * ir) * omj + (c.w * omi + d.w * ir) * jr;
    return out;
}

__global__ void __launch_bounds__(256)
triplane_kernel(const int*   __restrict__ m,
                const float* __restrict__ h,
                const float* __restrict__ u,
                const float* __restrict__ v,
                const float* __restrict__ Fxy,
                const float* __restrict__ Fxu,
                const float* __restrict__ Fxv,
                const float* __restrict__ Fyu,
                const float* __restrict__ Fyv,
                const float* __restrict__ Fuv,
                float4*      __restrict__ out,   // [N, 24] float4 view of [N, 96] f32
                int N) {
    int gid = blockIdx.x * blockDim.x + threadIdx.x;
    int pt  = gid >> 2;          // point index
    int q   = gid & 3;           // which float4 of the 16-channel latent
    if (pt >= N) return;

    int   mi = m[pt];
    float hx = h[2 * pt + 0];
    float hy = h[2 * pt + 1];
    float uu = u[pt];
    float vv = v[pt];

    float ind_hx = (hx + 1.0f) / 2.0f * (float)NHX;
    float ind_hy = (hy + 1.0f) / 2.0f * (float)NHY;
    float ind_u  = uu * (float)NU;
    float ind_v  = vv * (float)NV;

    int x1, x2, y1, y2, u1, u2, v1, v2;
    float xr, yr, ur, vr;
    axis(ind_hx, NHX, x1, x2, xr);
    axis(ind_hy, NHY, y1, y2, yr);
    axis(ind_u,  NU,  u1, u2, ur);
    axis(ind_v,  NV,  v1, v2, vr);

    float4* o = out + (size_t)pt * (NPLANES * (LCH / 4));

    // concat order: xy, xu, xv, yu, yv, uv
    o[0 * 4 + q] = bilerp4(Fxy, mi, NHX, NHY, x1, x2, xr, y1, y2, yr, q);
    o[1 * 4 + q] = bilerp4(Fxu, mi, NHX, NU,  x1, x2, xr, u1, u2, ur, q);
    o[2 * 4 + q] = bilerp4(Fxv, mi, NHX, NV,  x1, x2, xr, v1, v2, vr, q);
    o[3 * 4 + q] = bilerp4(Fyu, mi, NHY, NU,  y1, y2, yr, u1, u2, ur, q);
    o[4 * 4 + q] = bilerp4(Fyv, mi, NHY, NV,  y1, y2, yr, v1, v2, vr, q);
    o[5 * 4 + q] = bilerp4(Fuv, mi, NU,  NV,  u1, u2, ur, v1, v2, vr, q);
}

extern "C" void kernel_launch(void* const* d_in, const int* in_sizes, int n_in,
                              void* d_out, int out_size) {
    // metadata order: r, m, h, u, v, Fxy, Fxu, Fxv, Fyu, Fyv, Fuv   (r unused)
    const int*   m   = (const int*)  d_in[1];
    const float* h   = (const float*)d_in[2];
    const float* u   = (const float*)d_in[3];
    const float* v   = (const float*)d_in[4];
    const float* Fxy = (const float*)d_in[5];
    const float* Fxu = (const float*)d_in[6];
    const float* Fxv = (const float*)d_in[7];
    const float* Fyu = (const float*)d_in[8];
    const float* Fyv = (const float*)d_in[9];
    const float* Fuv = (const float*)d_in[10];

    int N = in_sizes[1];  // number of points (m has N elements)

    long long total_threads = (long long)N * 4;
    int threads = 256;
    int blocks  = (int)((total_threads + threads - 1) / threads);

    triplane_kernel<<<blocks, threads>>>(m, h, u, v,
                                         Fxy, Fxu, Fxv, Fyu, Fyv, Fuv,
                                         (float4*)d_out, N);
}